// round 4
// baseline (speedup 1.0000x reference)
#include <cuda_runtime.h>
#include <math.h>

#define T_FAST 512
#define T_SLOW 128
#define BB 32
#define DD 1024
#define HH 256
#define NF (T_FAST*BB*DD)   // 16777216
#define NS (T_SLOW*BB*DD)   // 4194304

// ---------------- scratch (static device memory; no allocs) ----------------
__device__ float g_glob[4*BB*DD];      // per-stream time-mean [4][32][1024]
__device__ float g_hbuf[8*BB*HH];      // MLP hidden (8 relevant pairs)
__device__ float g_scores[16*BB];      // sigmoid scores, indexed by full pair p
__device__ int   g_cond[16];           // cond flags, indexed by full pair p
__device__ float g_Y[2*NS];            // s2f 1x1-conv at native T=128, for i=2 (slot0), i=3 (slot1)

// relevant pairs (i,j,p=i*4+j): (2,0) (3,0) (2,1) (3,1) (0,2) (1,2) (0,3) (1,3)
__constant__ int c_pi[8] = {2,3,2,3,0,1,0,1};
__constant__ int c_pj[8] = {0,0,1,1,2,2,3,3};
__constant__ int c_pp[8] = {8,12,9,13,2,6,3,7};

// selection: for fast output j in {0,1}: i=3 wins if cond(3,j), else i=2 if cond(2,j), else none
__device__ __forceinline__ int sel_s2f(int j) {
    if (g_cond[12 + j]) return 3;
    if (g_cond[8 + j])  return 2;
    return -1;
}
// for slow output j in {2,3}: i=1 wins if cond(1,j), else i=0 if cond(0,j), else none
__device__ __forceinline__ int sel_f2s(int j) {
    if (g_cond[4 + j]) return 1;
    if (g_cond[j])     return 0;
    return -1;
}

// ---------------- K1: time means ----------------
__global__ void k_globals(const float* __restrict__ f0, const float* __restrict__ f1,
                          const float* __restrict__ f2, const float* __restrict__ f3) {
    int idx = blockIdx.x*blockDim.x + threadIdx.x;   // 4*32*1024 = 131072
    if (idx >= 4*BB*DD) return;
    int i  = idx >> 15;
    int bd = idx & 32767;
    int b = bd >> 10, d = bd & 1023;
    const float* f = (i==0)?f0:(i==1)?f1:(i==2)?f2:f3;
    int T = (i < 2) ? T_FAST : T_SLOW;
    float s = 0.f;
    for (int t = 0; t < T; t++) s += f[((size_t)t*BB + b)*DD + d];
    g_glob[idx] = s / (float)T;
}

// ---------------- K2a: hidden layer, one block per (b, pair) ----------------
__global__ void k_mlp1(const float* __restrict__ w1, const float* __restrict__ b1) {
    __shared__ float pv[2*DD];
    int b = blockIdx.x, lp = blockIdx.y, tid = threadIdx.x;
    int i = c_pi[lp], j = c_pj[lp], p = c_pp[lp];
    for (int c = tid; c < 2*DD; c += 256)
        pv[c] = (c < DD) ? g_glob[(i*BB+b)*DD + c] : g_glob[(j*BB+b)*DD + (c-DD)];
    __syncthreads();
    const float* w = w1 + (size_t)p*2*DD*HH + tid;
    float acc = b1[p*HH + tid];
    #pragma unroll 8
    for (int c = 0; c < 2*DD; c++) acc += pv[c] * w[(size_t)c*HH];
    g_hbuf[(lp*BB + b)*HH + tid] = fmaxf(acc, 0.f);
}

// ---------------- K2b: scores + conds, one block (32 thr) per pair ----------------
__global__ void k_mlp2(const float* __restrict__ w2, const float* __restrict__ b2) {
    int lp = blockIdx.x, b = threadIdx.x, p = c_pp[lp];
    const float* hb = g_hbuf + (lp*BB + b)*HH;
    const float* w  = w2 + p*HH;
    float acc = 0.f;
    #pragma unroll 8
    for (int h = 0; h < HH; h++) acc += hb[h]*w[h];
    float s = 1.f/(1.f + expf(-(acc + b2[p])));
    g_scores[p*BB + b] = s;
    float sum = s;
    #pragma unroll
    for (int o = 16; o; o >>= 1) sum += __shfl_xor_sync(0xffffffffu, sum, o);
    if (b == 0) g_cond[p] = (sum * (1.f/32.f) >= 0.3f) ? 1 : 0;
}

// ---------------- K3: 1x1 conv at native slow rate: Y[n][o] = sum_c W[o][c]*F[n][c] ----------------
// 128x128 tile, BK=8, 256 threads, 8x8 microtile. Guarded by need flag.
__global__ void __launch_bounds__(256) k_y(const float* __restrict__ W,
                                           const float* __restrict__ F, int ib) {
    int i = 2 + ib;
    if (sel_s2f(0) != i && sel_s2f(1) != i) return;
    __shared__ float As[8][128];
    __shared__ float Bs[8][128];
    int tid = threadIdx.x;
    int O0 = blockIdx.x * 128;          // 8 tiles over o
    int N0 = blockIdx.y * 128;          // 32 tiles over n = t*32+b
    int tx = tid & 15, ty = tid >> 4;
    int so = tid >> 1, sh = (tid & 1)*4;
    float acc[8][8];
    #pragma unroll
    for (int a = 0; a < 8; a++)
        #pragma unroll
        for (int c = 0; c < 8; c++) acc[a][c] = 0.f;

    for (int kc = 0; kc < DD; kc += 8) {
        float4 av = *(const float4*)&W[(size_t)(O0+so)*DD + kc + sh];
        float4 bv = *(const float4*)&F[(size_t)(N0+so)*DD + kc + sh];
        __syncthreads();
        As[sh+0][so] = av.x; As[sh+1][so] = av.y; As[sh+2][so] = av.z; As[sh+3][so] = av.w;
        Bs[sh+0][so] = bv.x; Bs[sh+1][so] = bv.y; Bs[sh+2][so] = bv.z; Bs[sh+3][so] = bv.w;
        __syncthreads();
        #pragma unroll
        for (int k = 0; k < 8; k++) {
            float a[8], bb_[8];
            *(float4*)&a[0]   = *(const float4*)&As[k][ty*8];
            *(float4*)&a[4]   = *(const float4*)&As[k][ty*8+4];
            *(float4*)&bb_[0] = *(const float4*)&Bs[k][tx*8];
            *(float4*)&bb_[4] = *(const float4*)&Bs[k][tx*8+4];
            #pragma unroll
            for (int oi = 0; oi < 8; oi++)
                #pragma unroll
                for (int nj = 0; nj < 8; nj++)
                    acc[oi][nj] += a[oi]*bb_[nj];
        }
    }
    float* Yp = g_Y + (size_t)ib*NS;
    #pragma unroll
    for (int nj = 0; nj < 8; nj++) {
        int n = N0 + tx*8 + nj;
        float* row = Yp + (size_t)n*DD + O0 + ty*8;
        float4 v0 = make_float4(acc[0][nj], acc[1][nj], acc[2][nj], acc[3][nj]);
        float4 v1 = make_float4(acc[4][nj], acc[5][nj], acc[6][nj], acc[7][nj]);
        *(float4*)row     = v0;
        *(float4*)(row+4) = v1;
    }
}

// ---------------- K4: fast-output epilogue (lerp of Y + bias, residual, or copy) ----------------
__global__ void k_epi_fast(const float* __restrict__ Fj, const float* __restrict__ bias,
                           float* __restrict__ out, int j) {
    int gid = blockIdx.x*256 + threadIdx.x;   // NF/4 float4 elements
    int n = gid >> 8;            // 256 float4 per 1024-row
    int o = (gid & 255) * 4;
    int t = n >> 5, b = n & 31;
    float4 fv = *(const float4*)&Fj[(size_t)n*DD + o];
    int s = sel_s2f(j);
    float4 res;
    if (s < 0) {
        res = fv;
    } else {
        int ib = s - 2;
        float sc = g_scores[(s*4 + j)*BB + b];
        float src = 0.25f*(float)t - 0.375f;
        src = fminf(fmaxf(src, 0.f), 127.f);
        float fi0 = floorf(src);
        int i0 = (int)fi0;
        int i1 = min(i0 + 1, 127);
        float w = src - fi0;
        const float* Yp = g_Y + (size_t)ib*NS;
        float4 y0 = *(const float4*)&Yp[((size_t)i0*BB + b)*DD + o];
        float4 y1 = *(const float4*)&Yp[((size_t)i1*BB + b)*DD + o];
        float4 bv = *(const float4*)&bias[o];
        float om = 1.f - w;
        res.x = fv.x + sc*(om*y0.x + w*y1.x + bv.x);
        res.y = fv.y + sc*(om*y0.y + w*y1.y + bv.y);
        res.z = fv.z + sc*(om*y0.z + w*y1.z + bv.z);
        res.w = fv.w + sc*(om*y0.w + w*y1.w + bv.w);
    }
    *(float4*)&out[(size_t)n*DD + o] = res;
}

// ---------------- K5: fast->slow strided conv (K=5, stride 4, pad 2), fused residual ----------------
// M=1024 (o) x N=4096 (n = t_o*32+b) x K=(1024 c x 5 k). 128x128 tiles, c-chunk 8.
__global__ void __launch_bounds__(256) k_f2s(const float* __restrict__ f0,
                                             const float* __restrict__ f1,
                                             const float* __restrict__ fj,
                                             const float* __restrict__ wAll,
                                             float* __restrict__ out, int j) {
    int s = sel_f2s(j);
    if (s < 0) return;
    const float* F = s ? f1 : f0;
    int g = (j == 2) ? (s ? 2 : 0) : (s ? 3 : 1);   // F2S_IDX[(i,j)]
    const float* W = wAll + (size_t)g*DD*DD*5;
    int p = s*4 + j;

    __shared__ float As[40][128];          // (c,k) x o
    __shared__ float Fs[8][18][36];        // c x t' x b  (t' in [0,17), padded strides)
    int tid = threadIdx.x;
    int O0 = blockIdx.x * 128;             // 8 tiles
    int T0 = blockIdx.y * 4;               // 32 tiles over t_o
    int tx = tid & 15, ty = tid >> 4;
    int to_loc = tx >> 2;                  // 0..3 (t_o within tile)
    int b0 = (tx & 3) * 8;                 // 8 consecutive b per thread
    float acc[8][8];
    #pragma unroll
    for (int a = 0; a < 8; a++)
        #pragma unroll
        for (int c = 0; c < 8; c++) acc[a][c] = 0.f;

    int so = tid >> 1;                     // o for A staging
    int qb = (tid & 1) * 20;               // (c,k) flat offset half

    for (int c0 = 0; c0 < DD; c0 += 8) {
        // A: 40 consecutive (c,k) per o (w layout contiguous in k then c)
        float wa[20];
        {
            const float* wp = W + (size_t)(O0+so)*(DD*5) + c0*5 + qb;
            #pragma unroll
            for (int u = 0; u < 5; u++) {
                float4 v = *(const float4*)(wp + u*4);
                wa[u*4+0] = v.x; wa[u*4+1] = v.y; wa[u*4+2] = v.z; wa[u*4+3] = v.w;
            }
        }
        // F: 17 t' x 32 b pairs, 8 consecutive c each
        float4 fv[3][2];
        int pt[3], pb[3];
        #pragma unroll
        for (int it = 0; it < 3; it++) {
            int pr = tid + it*256;
            int valid = (pr < 544);
            int tp = valid ? (pr >> 5) : 0;
            int bp = pr & 31;
            pt[it] = tp; pb[it] = bp;
            int t = 4*T0 - 2 + tp;
            if (valid && t >= 0 && t < T_FAST) {
                const float* fp = &F[((size_t)t*BB + bp)*DD + c0];
                fv[it][0] = *(const float4*)fp;
                fv[it][1] = *(const float4*)(fp + 4);
            } else {
                fv[it][0] = make_float4(0.f,0.f,0.f,0.f);
                fv[it][1] = make_float4(0.f,0.f,0.f,0.f);
            }
        }
        __syncthreads();
        #pragma unroll
        for (int u = 0; u < 20; u++) As[qb + u][so] = wa[u];
        #pragma unroll
        for (int it = 0; it < 3; it++) {
            int pr = tid + it*256;
            if (pr < 544) {
                Fs[0][pt[it]][pb[it]] = fv[it][0].x;
                Fs[1][pt[it]][pb[it]] = fv[it][0].y;
                Fs[2][pt[it]][pb[it]] = fv[it][0].z;
                Fs[3][pt[it]][pb[it]] = fv[it][0].w;
                Fs[4][pt[it]][pb[it]] = fv[it][1].x;
                Fs[5][pt[it]][pb[it]] = fv[it][1].y;
                Fs[6][pt[it]][pb[it]] = fv[it][1].z;
                Fs[7][pt[it]][pb[it]] = fv[it][1].w;
            }
        }
        __syncthreads();
        #pragma unroll
        for (int cc = 0; cc < 8; cc++) {
            #pragma unroll
            for (int k = 0; k < 5; k++) {
                int q = cc*5 + k;
                float a[8], bb_[8];
                *(float4*)&a[0] = *(const float4*)&As[q][ty*8];
                *(float4*)&a[4] = *(const float4*)&As[q][ty*8+4];
                const float* fr = &Fs[cc][4*to_loc + k][b0];
                *(float4*)&bb_[0] = *(const float4*)fr;
                *(float4*)&bb_[4] = *(const float4*)(fr + 4);
                #pragma unroll
                for (int oi = 0; oi < 8; oi++)
                    #pragma unroll
                    for (int bj = 0; bj < 8; bj++)
                        acc[oi][bj] += a[oi]*bb_[bj];
            }
        }
        __syncthreads();
    }
    // fused residual epilogue: out = feat_j + score[b]*down
    #pragma unroll
    for (int bj = 0; bj < 8; bj++) {
        int b = b0 + bj;
        int n = (T0 + to_loc)*BB + b;
        float sc = g_scores[p*BB + b];
        const float* fr = &fj[(size_t)n*DD + O0 + ty*8];
        float*       orr = &out[(size_t)n*DD + O0 + ty*8];
        float4 fa = *(const float4*)fr;
        float4 fb2 = *(const float4*)(fr + 4);
        float4 r0, r1;
        r0.x = fa.x + sc*acc[0][bj]; r0.y = fa.y + sc*acc[1][bj];
        r0.z = fa.z + sc*acc[2][bj]; r0.w = fa.w + sc*acc[3][bj];
        r1.x = fb2.x + sc*acc[4][bj]; r1.y = fb2.y + sc*acc[5][bj];
        r1.z = fb2.z + sc*acc[6][bj]; r1.w = fb2.w + sc*acc[7][bj];
        *(float4*)orr       = r0;
        *(float4*)(orr + 4) = r1;
    }
}

// ---------------- K6: fallback copy for slow outputs (runs only if no conv selected) ----------------
__global__ void k_copy_slow(const float* __restrict__ fj, float* __restrict__ out, int j) {
    if (sel_f2s(j) >= 0) return;
    int gid = blockIdx.x*256 + threadIdx.x;    // NS/4 float4s
    ((float4*)out)[gid] = ((const float4*)fj)[gid];
}

extern "C" void kernel_launch(void* const* d_in, const int* in_sizes, int n_in,
                              void* d_out, int out_size) {
    const float* f0    = (const float*)d_in[0];
    const float* f1    = (const float*)d_in[1];
    const float* f2    = (const float*)d_in[2];
    const float* f3    = (const float*)d_in[3];
    const float* w1    = (const float*)d_in[4];
    const float* b1    = (const float*)d_in[5];
    const float* w2    = (const float*)d_in[6];
    const float* b2    = (const float*)d_in[7];
    const float* s2fw  = (const float*)d_in[8];
    const float* s2fb  = (const float*)d_in[9];
    const float* f2sw  = (const float*)d_in[10];
    float* out = (float*)d_out;

    k_globals<<<(4*BB*DD + 255)/256, 256>>>(f0, f1, f2, f3);
    k_mlp1<<<dim3(BB, 8), 256>>>(w1, b1);
    k_mlp2<<<8, 32>>>(w2, b2);

    // s2f path: 1x1 conv at T=128 for needed i (guarded), then lerp epilogues
    k_y<<<dim3(8, 32), 256>>>(s2fw, f2, 0);
    k_y<<<dim3(8, 32), 256>>>(s2fw, f3, 1);
    k_epi_fast<<<NF/4/256, 256>>>(f0, s2fb, out, 0);
    k_epi_fast<<<NF/4/256, 256>>>(f1, s2fb, out + NF, 1);

    // f2s path: strided conv + residual for selected i (guarded), else copy
    k_f2s<<<dim3(8, 32), 256>>>(f0, f1, f2, f2sw, out + 2*(size_t)NF, 2);
    k_f2s<<<dim3(8, 32), 256>>>(f0, f1, f3, f2sw, out + 2*(size_t)NF + NS, 3);
    k_copy_slow<<<NS/4/256, 256>>>(f2, out + 2*(size_t)NF, 2);
    k_copy_slow<<<NS/4/256, 256>>>(f3, out + 2*(size_t)NF + NS, 3);
}

// round 6
// speedup vs baseline: 1.0001x; 1.0001x over previous
#include <cuda_runtime.h>
#include <math.h>

#define T_FAST 512
#define T_SLOW 128
#define BB 32
#define DD 1024
#define HH 256
#define NF (T_FAST*BB*DD)   // 16777216
#define NS (T_SLOW*BB*DD)   // 4194304

// ---------------- scratch (static device memory; no allocs) ----------------
__device__ float g_glob[4*BB*DD];      // per-stream time-mean [4][32][1024]
__device__ float g_hbuf[8*BB*HH];      // MLP hidden (8 relevant pairs)
__device__ float g_scores[16*BB];      // sigmoid scores, indexed by full pair p
__device__ int   g_cond[16];           // cond flags, indexed by full pair p
__device__ float g_Y[2*NS];            // s2f 1x1-conv at native T=128, for i=2 (slot0), i=3 (slot1)

// relevant pairs (i,j,p=i*4+j): (2,0) (3,0) (2,1) (3,1) (0,2) (1,2) (0,3) (1,3)
__constant__ int c_pi[8] = {2,3,2,3,0,1,0,1};
__constant__ int c_pj[8] = {0,0,1,1,2,2,3,3};
__constant__ int c_pp[8] = {8,12,9,13,2,6,3,7};

// selection: for fast output j in {0,1}: i=3 wins if cond(3,j), else i=2 if cond(2,j), else none
__device__ __forceinline__ int sel_s2f(int j) {
    if (g_cond[12 + j]) return 3;
    if (g_cond[8 + j])  return 2;
    return -1;
}
// for slow output j in {2,3}: i=1 wins if cond(1,j), else i=0 if cond(0,j), else none
__device__ __forceinline__ int sel_f2s(int j) {
    if (g_cond[4 + j]) return 1;
    if (g_cond[j])     return 0;
    return -1;
}

// ---------------- K1: time means ----------------
__global__ void k_globals(const float* __restrict__ f0, const float* __restrict__ f1,
                          const float* __restrict__ f2, const float* __restrict__ f3) {
    int idx = blockIdx.x*blockDim.x + threadIdx.x;   // 4*32*1024 = 131072
    if (idx >= 4*BB*DD) return;
    int i  = idx >> 15;
    int bd = idx & 32767;
    int b = bd >> 10, d = bd & 1023;
    const float* f = (i==0)?f0:(i==1)?f1:(i==2)?f2:f3;
    int T = (i < 2) ? T_FAST : T_SLOW;
    float s = 0.f;
    for (int t = 0; t < T; t++) s += f[((size_t)t*BB + b)*DD + d];
    g_glob[idx] = s / (float)T;
}

// ---------------- K2a: hidden layer, one block per (b, pair) ----------------
__global__ void k_mlp1(const float* __restrict__ w1, const float* __restrict__ b1) {
    __shared__ float pv[2*DD];
    int b = blockIdx.x, lp = blockIdx.y, tid = threadIdx.x;
    int i = c_pi[lp], j = c_pj[lp], p = c_pp[lp];
    for (int c = tid; c < 2*DD; c += 256)
        pv[c] = (c < DD) ? g_glob[(i*BB+b)*DD + c] : g_glob[(j*BB+b)*DD + (c-DD)];
    __syncthreads();
    const float* w = w1 + (size_t)p*2*DD*HH + tid;
    float acc = b1[p*HH + tid];
    #pragma unroll 8
    for (int c = 0; c < 2*DD; c++) acc += pv[c] * w[(size_t)c*HH];
    g_hbuf[(lp*BB + b)*HH + tid] = fmaxf(acc, 0.f);
}

// ---------------- K2b: scores + conds, one block (32 thr) per pair ----------------
__global__ void k_mlp2(const float* __restrict__ w2, const float* __restrict__ b2) {
    int lp = blockIdx.x, b = threadIdx.x, p = c_pp[lp];
    const float* hb = g_hbuf + (lp*BB + b)*HH;
    const float* w  = w2 + p*HH;
    float acc = 0.f;
    #pragma unroll 8
    for (int h = 0; h < HH; h++) acc += hb[h]*w[h];
    float s = 1.f/(1.f + expf(-(acc + b2[p])));
    g_scores[p*BB + b] = s;
    float sum = s;
    #pragma unroll
    for (int o = 16; o; o >>= 1) sum += __shfl_xor_sync(0xffffffffu, sum, o);
    if (b == 0) g_cond[p] = (sum * (1.f/32.f) >= 0.3f) ? 1 : 0;
}

// ---------------- K3: 1x1 conv at native slow rate: Y[n][o] = sum_c W[o][c]*F[n][c] ----------------
// 128x128 tile, BK=8, 256 threads, 8x8 microtile. Guarded by need flag.
__global__ void __launch_bounds__(256) k_y(const float* __restrict__ W,
                                           const float* __restrict__ F, int ib) {
    int i = 2 + ib;
    if (sel_s2f(0) != i && sel_s2f(1) != i) return;
    __shared__ float As[8][128];
    __shared__ float Bs[8][128];
    int tid = threadIdx.x;
    int O0 = blockIdx.x * 128;          // 8 tiles over o
    int N0 = blockIdx.y * 128;          // 32 tiles over n = t*32+b
    int tx = tid & 15, ty = tid >> 4;
    int so = tid >> 1, sh = (tid & 1)*4;
    float acc[8][8];
    #pragma unroll
    for (int a = 0; a < 8; a++)
        #pragma unroll
        for (int c = 0; c < 8; c++) acc[a][c] = 0.f;

    for (int kc = 0; kc < DD; kc += 8) {
        float4 av = *(const float4*)&W[(size_t)(O0+so)*DD + kc + sh];
        float4 bv = *(const float4*)&F[(size_t)(N0+so)*DD + kc + sh];
        __syncthreads();
        As[sh+0][so] = av.x; As[sh+1][so] = av.y; As[sh+2][so] = av.z; As[sh+3][so] = av.w;
        Bs[sh+0][so] = bv.x; Bs[sh+1][so] = bv.y; Bs[sh+2][so] = bv.z; Bs[sh+3][so] = bv.w;
        __syncthreads();
        #pragma unroll
        for (int k = 0; k < 8; k++) {
            float a[8], bb_[8];
            *(float4*)&a[0]   = *(const float4*)&As[k][ty*8];
            *(float4*)&a[4]   = *(const float4*)&As[k][ty*8+4];
            *(float4*)&bb_[0] = *(const float4*)&Bs[k][tx*8];
            *(float4*)&bb_[4] = *(const float4*)&Bs[k][tx*8+4];
            #pragma unroll
            for (int oi = 0; oi < 8; oi++)
                #pragma unroll
                for (int nj = 0; nj < 8; nj++)
                    acc[oi][nj] += a[oi]*bb_[nj];
        }
    }
    float* Yp = g_Y + (size_t)ib*NS;
    #pragma unroll
    for (int nj = 0; nj < 8; nj++) {
        int n = N0 + tx*8 + nj;
        float* row = Yp + (size_t)n*DD + O0 + ty*8;
        float4 v0 = make_float4(acc[0][nj], acc[1][nj], acc[2][nj], acc[3][nj]);
        float4 v1 = make_float4(acc[4][nj], acc[5][nj], acc[6][nj], acc[7][nj]);
        *(float4*)row     = v0;
        *(float4*)(row+4) = v1;
    }
}

// ---------------- K4: fast-output epilogue (lerp of Y + bias, residual, or copy) ----------------
__global__ void k_epi_fast(const float* __restrict__ Fj, const float* __restrict__ bias,
                           float* __restrict__ out, int j) {
    int gid = blockIdx.x*256 + threadIdx.x;   // NF/4 float4 elements
    int n = gid >> 8;            // 256 float4 per 1024-row
    int o = (gid & 255) * 4;
    int t = n >> 5, b = n & 31;
    float4 fv = *(const float4*)&Fj[(size_t)n*DD + o];
    int s = sel_s2f(j);
    float4 res;
    if (s < 0) {
        res = fv;
    } else {
        int ib = s - 2;
        float sc = g_scores[(s*4 + j)*BB + b];
        float src = 0.25f*(float)t - 0.375f;
        src = fminf(fmaxf(src, 0.f), 127.f);
        float fi0 = floorf(src);
        int i0 = (int)fi0;
        int i1 = min(i0 + 1, 127);
        float w = src - fi0;
        const float* Yp = g_Y + (size_t)ib*NS;
        float4 y0 = *(const float4*)&Yp[((size_t)i0*BB + b)*DD + o];
        float4 y1 = *(const float4*)&Yp[((size_t)i1*BB + b)*DD + o];
        float4 bv = *(const float4*)&bias[o];
        float om = 1.f - w;
        res.x = fv.x + sc*(om*y0.x + w*y1.x + bv.x);
        res.y = fv.y + sc*(om*y0.y + w*y1.y + bv.y);
        res.z = fv.z + sc*(om*y0.z + w*y1.z + bv.z);
        res.w = fv.w + sc*(om*y0.w + w*y1.w + bv.w);
    }
    *(float4*)&out[(size_t)n*DD + o] = res;
}

// ---------------- K5: fast->slow strided conv (K=5, stride 4, pad 2), fused residual ----------------
// M=1024 (o) x N=4096 (n = t_o*32+b) x K=(1024 c x 5 k). 128x128 tiles, c-chunk 8.
__global__ void __launch_bounds__(256) k_f2s(const float* __restrict__ f0,
                                             const float* __restrict__ f1,
                                             const float* __restrict__ fj,
                                             const float* __restrict__ wAll,
                                             float* __restrict__ out, int j) {
    int s = sel_f2s(j);
    if (s < 0) return;
    const float* F = s ? f1 : f0;
    int g = (j == 2) ? (s ? 2 : 0) : (s ? 3 : 1);   // F2S_IDX[(i,j)]
    const float* W = wAll + (size_t)g*DD*DD*5;
    int p = s*4 + j;

    __shared__ float As[40][128];          // (c,k) x o
    __shared__ float Fs[8][18][36];        // c x t' x b  (t' in [0,17), padded strides)
    int tid = threadIdx.x;
    int O0 = blockIdx.x * 128;             // 8 tiles
    int T0 = blockIdx.y * 4;               // 32 tiles over t_o
    int tx = tid & 15, ty = tid >> 4;
    int to_loc = tx >> 2;                  // 0..3 (t_o within tile)
    int b0 = (tx & 3) * 8;                 // 8 consecutive b per thread
    float acc[8][8];
    #pragma unroll
    for (int a = 0; a < 8; a++)
        #pragma unroll
        for (int c = 0; c < 8; c++) acc[a][c] = 0.f;

    int so = tid >> 1;                     // o for A staging
    int qb = (tid & 1) * 20;               // (c,k) flat offset half

    for (int c0 = 0; c0 < DD; c0 += 8) {
        // A: 40 consecutive (c,k) per o (w layout contiguous in k then c)
        float wa[20];
        {
            const float* wp = W + (size_t)(O0+so)*(DD*5) + c0*5 + qb;
            #pragma unroll
            for (int u = 0; u < 5; u++) {
                float4 v = *(const float4*)(wp + u*4);
                wa[u*4+0] = v.x; wa[u*4+1] = v.y; wa[u*4+2] = v.z; wa[u*4+3] = v.w;
            }
        }
        // F: 17 t' x 32 b pairs, 8 consecutive c each
        float4 fv[3][2];
        int pt[3], pb[3];
        #pragma unroll
        for (int it = 0; it < 3; it++) {
            int pr = tid + it*256;
            int valid = (pr < 544);
            int tp = valid ? (pr >> 5) : 0;
            int bp = pr & 31;
            pt[it] = tp; pb[it] = bp;
            int t = 4*T0 - 2 + tp;
            if (valid && t >= 0 && t < T_FAST) {
                const float* fp = &F[((size_t)t*BB + bp)*DD + c0];
                fv[it][0] = *(const float4*)fp;
                fv[it][1] = *(const float4*)(fp + 4);
            } else {
                fv[it][0] = make_float4(0.f,0.f,0.f,0.f);
                fv[it][1] = make_float4(0.f,0.f,0.f,0.f);
            }
        }
        __syncthreads();
        #pragma unroll
        for (int u = 0; u < 20; u++) As[qb + u][so] = wa[u];
        #pragma unroll
        for (int it = 0; it < 3; it++) {
            int pr = tid + it*256;
            if (pr < 544) {
                Fs[0][pt[it]][pb[it]] = fv[it][0].x;
                Fs[1][pt[it]][pb[it]] = fv[it][0].y;
                Fs[2][pt[it]][pb[it]] = fv[it][0].z;
                Fs[3][pt[it]][pb[it]] = fv[it][0].w;
                Fs[4][pt[it]][pb[it]] = fv[it][1].x;
                Fs[5][pt[it]][pb[it]] = fv[it][1].y;
                Fs[6][pt[it]][pb[it]] = fv[it][1].z;
                Fs[7][pt[it]][pb[it]] = fv[it][1].w;
            }
        }
        __syncthreads();
        #pragma unroll
        for (int cc = 0; cc < 8; cc++) {
            #pragma unroll
            for (int k = 0; k < 5; k++) {
                int q = cc*5 + k;
                float a[8], bb_[8];
                *(float4*)&a[0] = *(const float4*)&As[q][ty*8];
                *(float4*)&a[4] = *(const float4*)&As[q][ty*8+4];
                const float* fr = &Fs[cc][4*to_loc + k][b0];
                *(float4*)&bb_[0] = *(const float4*)fr;
                *(float4*)&bb_[4] = *(const float4*)(fr + 4);
                #pragma unroll
                for (int oi = 0; oi < 8; oi++)
                    #pragma unroll
                    for (int bj = 0; bj < 8; bj++)
                        acc[oi][bj] += a[oi]*bb_[bj];
            }
        }
        __syncthreads();
    }
    // fused residual epilogue: out = feat_j + score[b]*down
    #pragma unroll
    for (int bj = 0; bj < 8; bj++) {
        int b = b0 + bj;
        int n = (T0 + to_loc)*BB + b;
        float sc = g_scores[p*BB + b];
        const float* fr = &fj[(size_t)n*DD + O0 + ty*8];
        float*       orr = &out[(size_t)n*DD + O0 + ty*8];
        float4 fa = *(const float4*)fr;
        float4 fb2 = *(const float4*)(fr + 4);
        float4 r0, r1;
        r0.x = fa.x + sc*acc[0][bj]; r0.y = fa.y + sc*acc[1][bj];
        r0.z = fa.z + sc*acc[2][bj]; r0.w = fa.w + sc*acc[3][bj];
        r1.x = fb2.x + sc*acc[4][bj]; r1.y = fb2.y + sc*acc[5][bj];
        r1.z = fb2.z + sc*acc[6][bj]; r1.w = fb2.w + sc*acc[7][bj];
        *(float4*)orr       = r0;
        *(float4*)(orr + 4) = r1;
    }
}

// ---------------- K6: fallback copy for slow outputs (runs only if no conv selected) ----------------
__global__ void k_copy_slow(const float* __restrict__ fj, float* __restrict__ out, int j) {
    if (sel_f2s(j) >= 0) return;
    int gid = blockIdx.x*256 + threadIdx.x;    // NS/4 float4s
    ((float4*)out)[gid] = ((const float4*)fj)[gid];
}

extern "C" void kernel_launch(void* const* d_in, const int* in_sizes, int n_in,
                              void* d_out, int out_size) {
    const float* f0    = (const float*)d_in[0];
    const float* f1    = (const float*)d_in[1];
    const float* f2    = (const float*)d_in[2];
    const float* f3    = (const float*)d_in[3];
    const float* w1    = (const float*)d_in[4];
    const float* b1    = (const float*)d_in[5];
    const float* w2    = (const float*)d_in[6];
    const float* b2    = (const float*)d_in[7];
    const float* s2fw  = (const float*)d_in[8];
    const float* s2fb  = (const float*)d_in[9];
    const float* f2sw  = (const float*)d_in[10];
    float* out = (float*)d_out;

    k_globals<<<(4*BB*DD + 255)/256, 256>>>(f0, f1, f2, f3);
    k_mlp1<<<dim3(BB, 8), 256>>>(w1, b1);
    k_mlp2<<<8, 32>>>(w2, b2);

    // s2f path: 1x1 conv at T=128 for needed i (guarded), then lerp epilogues
    k_y<<<dim3(8, 32), 256>>>(s2fw, f2, 0);
    k_y<<<dim3(8, 32), 256>>>(s2fw, f3, 1);
    k_epi_fast<<<NF/4/256, 256>>>(f0, s2fb, out, 0);
    k_epi_fast<<<NF/4/256, 256>>>(f1, s2fb, out + NF, 1);

    // f2s path: strided conv + residual for selected i (guarded), else copy
    k_f2s<<<dim3(8, 32), 256>>>(f0, f1, f2, f2sw, out + 2*(size_t)NF, 2);
    k_f2s<<<dim3(8, 32), 256>>>(f0, f1, f3, f2sw, out + 2*(size_t)NF + NS, 3);
    k_copy_slow<<<NS/4/256, 256>>>(f2, out + 2*(size_t)NF, 2);
    k_copy_slow<<<NS/4/256, 256>>>(f3, out + 2*(size_t)NF + NS, 3);
}

// round 13
// speedup vs baseline: 2.3037x; 2.3034x over previous
#include <cuda_runtime.h>
#include <cuda_fp16.h>
#include <stdint.h>
#include <math.h>

#define T_FAST 512
#define T_SLOW 128
#define BB 32
#define DD 1024
#define HH 256
#define NF (T_FAST*BB*DD)   // 16777216
#define NS (T_SLOW*BB*DD)   // 4194304

// ---------------- static scratch (no allocs) ----------------
__device__ float g_glob[4*BB*DD];
__device__ float g_hbuf[8*BB*HH];
__device__ float g_scores[16*BB];
__device__ int   g_cond[16];
__device__ float g_Y[2*NS];
__device__ __half g_Fh[2*NF],  g_Fl[2*NF];              // fast feats hi/lo (slot=i)
__device__ __half g_Sh[2*NS],  g_Sl[2*NS];              // slow feats hi/lo (slot=i-2)
__device__ __half g_Wfh[2*5242880], g_Wfl[2*5242880];   // f2s W flat (o*5+k)*1024+c (slot=j-2)
__device__ __half g_Wsh[1024*1024], g_Wsl[1024*1024];   // s2f W [o][c]

__constant__ int c_pi[8] = {2,3,2,3,0,1,0,1};
__constant__ int c_pj[8] = {0,0,1,1,2,2,3,3};
__constant__ int c_pp[8] = {8,12,9,13,2,6,3,7};

__device__ __forceinline__ int sel_s2f(int j) {
    if (g_cond[12 + j]) return 3;
    if (g_cond[8 + j])  return 2;
    return -1;
}
__device__ __forceinline__ int sel_f2s(int j) {
    if (g_cond[4 + j]) return 1;
    if (g_cond[j])     return 0;
    return -1;
}

// ---------------- low-level helpers (all family-portable: sm_80-era) ----------------
__device__ __forceinline__ uint32_t smem_u32(const void* p){
    uint32_t a;
    asm("{ .reg .u64 t; cvta.to.shared.u64 t, %1; cvt.u32.u64 %0, t; }":"=r"(a):"l"(p));
    return a;
}
__device__ __forceinline__ void cpasync16(uint32_t d, const void* g, int sz){
    asm volatile("cp.async.cg.shared.global [%0], [%1], 16, %2;"
                 :: "r"(d), "l"(g), "r"(sz) : "memory");
}
__device__ __forceinline__ void ldm_x4(uint32_t r[4], uint32_t addr){
    asm volatile("ldmatrix.sync.aligned.m8n8.x4.shared.b16 {%0,%1,%2,%3}, [%4];"
                 : "=r"(r[0]), "=r"(r[1]), "=r"(r[2]), "=r"(r[3]) : "r"(addr));
}
__device__ __forceinline__ void mma16816(float d[4], const uint32_t a[4], uint32_t b0, uint32_t b1){
    asm volatile("mma.sync.aligned.m16n8k16.row.col.f32.f16.f16.f32 "
        "{%0,%1,%2,%3}, {%4,%5,%6,%7}, {%8,%9}, {%0,%1,%2,%3};"
        : "+f"(d[0]), "+f"(d[1]), "+f"(d[2]), "+f"(d[3])
        : "r"(a[0]), "r"(a[1]), "r"(a[2]), "r"(a[3]), "r"(b0), "r"(b1));
}

// smem layout: 4 arrays x 128 rows x 40 halves (80B padded stride), double buffered
#define ROWB 80
#define ARR_SZ 10240
#define OFF_AH 0
#define OFF_AL 10240
#define OFF_BH 20480
#define OFF_BL 30720
#define BUF_SZ 40960
#define SMEM_TOTAL (2*BUF_SZ)

// ---------------- conversions (fp16 hi/lo split) ----------------
__device__ __forceinline__ void cvt_store4h(float4 v, __half* ph, __half* pl){
    __half h0=__float2half_rn(v.x), h1=__float2half_rn(v.y);
    __half h2=__float2half_rn(v.z), h3=__float2half_rn(v.w);
    __half l0=__float2half_rn(v.x-__half2float(h0));
    __half l1=__float2half_rn(v.y-__half2float(h1));
    __half l2=__float2half_rn(v.z-__half2float(h2));
    __half l3=__float2half_rn(v.w-__half2float(h3));
    union { __half b[4]; uint2 u; } H, L;
    H.b[0]=h0; H.b[1]=h1; H.b[2]=h2; H.b[3]=h3;
    L.b[0]=l0; L.b[1]=l1; L.b[2]=l2; L.b[3]=l3;
    *(uint2*)ph = H.u;
    *(uint2*)pl = L.u;
}
__global__ void k_cvt_fast(const float* __restrict__ f, int i) {
    if (sel_f2s(2) != i && sel_f2s(3) != i) return;
    size_t idx = ((size_t)blockIdx.x*256 + threadIdx.x)*4;
    float4 v = *(const float4*)(f + idx);
    cvt_store4h(v, g_Fh + (size_t)i*NF + idx, g_Fl + (size_t)i*NF + idx);
}
__global__ void k_cvt_slow(const float* __restrict__ f, int ib) {
    int i = 2 + ib;
    if (sel_s2f(0) != i && sel_s2f(1) != i) return;
    size_t idx = ((size_t)blockIdx.x*256 + threadIdx.x)*4;
    float4 v = *(const float4*)(f + idx);
    cvt_store4h(v, g_Sh + (size_t)ib*NS + idx, g_Sl + (size_t)ib*NS + idx);
}
__global__ void k_cvt_ws2f(const float* __restrict__ w) {
    if (sel_s2f(0) < 0 && sel_s2f(1) < 0) return;
    size_t idx = ((size_t)blockIdx.x*256 + threadIdx.x)*4;
    float4 v = *(const float4*)(w + idx);
    cvt_store4h(v, g_Wsh + idx, g_Wsl + idx);
}
__global__ void k_cvt_wf2s(const float* __restrict__ wAll, int jb) {
    int j = 2 + jb;
    int s = sel_f2s(j);
    if (s < 0) return;
    int g = s*2 + jb;                                   // F2S_IDX[(s, j)]
    size_t flat = ((size_t)blockIdx.x*256 + threadIdx.x)*4;  // (o*5+k)*1024 + c
    int c  = (int)(flat & 1023);
    int ok = (int)(flat >> 10);
    int o = ok / 5, k = ok % 5;
    const float* src = wAll + ((size_t)(g*1024 + o)*1024 + c)*5 + k;
    float4 v = make_float4(src[0], src[5], src[10], src[15]);
    cvt_store4h(v, g_Wfh + (size_t)jb*5242880 + flat, g_Wfl + (size_t)jb*5242880 + flat);
}

// ---------------- K1: time means ----------------
__global__ void k_globals(const float* __restrict__ f0, const float* __restrict__ f1,
                          const float* __restrict__ f2, const float* __restrict__ f3) {
    int idx = blockIdx.x*blockDim.x + threadIdx.x;
    if (idx >= 4*BB*DD) return;
    int i  = idx >> 15;
    int bd = idx & 32767;
    int b = bd >> 10, d = bd & 1023;
    const float* f = (i==0)?f0:(i==1)?f1:(i==2)?f2:f3;
    int T = (i < 2) ? T_FAST : T_SLOW;
    float s = 0.f;
    for (int t = 0; t < T; t++) s += f[((size_t)t*BB + b)*DD + d];
    g_glob[idx] = s / (float)T;
}

// ---------------- K2: gating MLP ----------------
__global__ void k_mlp1(const float* __restrict__ w1, const float* __restrict__ b1) {
    __shared__ float pv[2*DD];
    int b = blockIdx.x, lp = blockIdx.y, tid = threadIdx.x;
    int i = c_pi[lp], j = c_pj[lp], p = c_pp[lp];
    for (int c = tid; c < 2*DD; c += 256)
        pv[c] = (c < DD) ? g_glob[(i*BB+b)*DD + c] : g_glob[(j*BB+b)*DD + (c-DD)];
    __syncthreads();
    const float* w = w1 + (size_t)p*2*DD*HH + tid;
    float acc = b1[p*HH + tid];
    #pragma unroll 8
    for (int c = 0; c < 2*DD; c++) acc += pv[c] * w[(size_t)c*HH];
    g_hbuf[(lp*BB + b)*HH + tid] = fmaxf(acc, 0.f);
}
__global__ void k_mlp2(const float* __restrict__ w2, const float* __restrict__ b2) {
    int lp = blockIdx.x, b = threadIdx.x, p = c_pp[lp];
    const float* hb = g_hbuf + (lp*BB + b)*HH;
    const float* w  = w2 + p*HH;
    float acc = 0.f;
    #pragma unroll 8
    for (int h = 0; h < HH; h++) acc += hb[h]*w[h];
    float s = 1.f/(1.f + expf(-(acc + b2[p])));
    g_scores[p*BB + b] = s;
    float sum = s;
    #pragma unroll
    for (int o = 16; o; o >>= 1) sum += __shfl_xor_sync(0xffffffffu, sum, o);
    if (b == 0) g_cond[p] = (sum * (1.f/32.f) >= 0.3f) ? 1 : 0;
}

// ---------------- unified mma.sync GEMM ----------------
// mode 0: s2f 1x1 conv at T=128 (K=1024), writes raw g_Y[jarg].
// mode 1: f2s strided conv (5 taps, K=5120), fused residual into out.
// Tiles: CTA 128(M=o) x 128(N=n), 8 warps (2M x 4N), warp 64x32, fp16 3-term split.
__device__ __forceinline__ void issue_stage(uint32_t sb, const __half* __restrict__ Ah,
        const __half* __restrict__ Al, const __half* __restrict__ Bh,
        const __half* __restrict__ Bl, int mode, int O0, int N0, int s, int tid) {
    int k  = mode ? (s >> 5) : 0;
    int c0 = mode ? ((s & 31) << 5) : (s << 5);
    int Tsrc = mode ? T_FAST : T_SLOW;
    #pragma unroll
    for (int h = 0; h < 2; h++) {
        int q = tid + h*256;
        int r = q >> 2, c = q & 3;
        uint32_t doff = (uint32_t)(r*ROWB + c*16);
        size_t aoff = mode ? ((((size_t)(O0+r)*5 + k) << 10) + c0 + c*8)
                           : (((size_t)(O0+r) << 10) + c0 + c*8);
        cpasync16(sb + OFF_AH + doff, Ah + aoff, 16);
        cpasync16(sb + OFF_AL + doff, Al + aoff, 16);
        int n = N0 + r;
        int t_ = mode ? (4*(n>>5) + k - 2) : (n>>5);
        int b_ = n & 31;
        bool ok = (t_ >= 0) && (t_ < Tsrc);
        size_t boff = (((size_t)(ok ? t_ : 0)*BB + b_) << 10) + c0 + c*8;
        int sz = ok ? 16 : 0;
        cpasync16(sb + OFF_BH + doff, Bh + boff, sz);
        cpasync16(sb + OFF_BL + doff, Bl + boff, sz);
    }
}

__global__ void __launch_bounds__(256) k_gemm(int mode, int jarg,
                                              const float* __restrict__ fj,
                                              float* __restrict__ out) {
    const __half *Ah, *Al, *Bh, *Bl;
    int p = 0;
    size_t yoff = 0;
    if (mode == 0) {
        int i = 2 + jarg;
        if (sel_s2f(0) != i && sel_s2f(1) != i) return;
        Ah = g_Wsh; Al = g_Wsl;
        Bh = g_Sh + (size_t)jarg*NS; Bl = g_Sl + (size_t)jarg*NS;
        yoff = (size_t)jarg*NS;
    } else {
        int s = sel_f2s(jarg);
        if (s < 0) return;
        int jb = jarg - 2;
        Ah = g_Wfh + (size_t)jb*5242880; Al = g_Wfl + (size_t)jb*5242880;
        Bh = g_Fh + (size_t)s*NF;        Bl = g_Fl + (size_t)s*NF;
        p = s*4 + jarg;
    }

    extern __shared__ char sm[];
    uint32_t smem_base = smem_u32(sm);
    int tid = threadIdx.x;
    int lane = tid & 31, wid = tid >> 5;
    int warp_m = wid & 1, warp_n = wid >> 1;
    int O0 = blockIdx.x * 128;
    int N0 = blockIdx.y * 128;

    // ldmatrix per-lane base offsets
    int a_row = warp_m*64 + (lane & 7) + ((lane >> 3) & 1)*8;
    int a_cb  = lane >> 4;                 // k-chunk offset (16B units)
    int b_row = warp_n*32 + (lane & 7) + (lane >> 4)*8;
    int b_cb  = (lane >> 3) & 1;

    float acc[4][4][4];
    #pragma unroll
    for (int mi = 0; mi < 4; mi++)
        #pragma unroll
        for (int ni = 0; ni < 4; ni++)
            #pragma unroll
            for (int e = 0; e < 4; e++) acc[mi][ni][e] = 0.f;

    int NSt = mode ? 160 : 32;
    issue_stage(smem_base, Ah, Al, Bh, Bl, mode, O0, N0, 0, tid);
    asm volatile("cp.async.commit_group;" ::: "memory");

    for (int s = 0; s < NSt; s++) {
        if (s + 1 < NSt) {
            issue_stage(smem_base + ((s+1)&1)*BUF_SZ, Ah, Al, Bh, Bl, mode, O0, N0, s+1, tid);
            asm volatile("cp.async.commit_group;" ::: "memory");
            asm volatile("cp.async.wait_group 1;" ::: "memory");
        } else {
            asm volatile("cp.async.wait_group 0;" ::: "memory");
        }
        __syncthreads();

        uint32_t sb = smem_base + (s&1)*BUF_SZ;
        #pragma unroll
        for (int kk8 = 0; kk8 <= 2; kk8 += 2) {
            uint32_t ah[4][4], al[4][4], bh[2][4], bl[2][4];
            #pragma unroll
            for (int mi = 0; mi < 4; mi++) {
                uint32_t ad = sb + (uint32_t)((a_row + mi*16)*ROWB + (kk8 + a_cb)*16);
                ldm_x4(ah[mi], ad + OFF_AH);
                ldm_x4(al[mi], ad + OFF_AL);
            }
            #pragma unroll
            for (int g = 0; g < 2; g++) {
                uint32_t bd = sb + (uint32_t)((b_row + g*16)*ROWB + (kk8 + b_cb)*16);
                ldm_x4(bh[g], bd + OFF_BH);
                ldm_x4(bl[g], bd + OFF_BL);
            }
            #pragma unroll
            for (int mi = 0; mi < 4; mi++)
                #pragma unroll
                for (int ni = 0; ni < 4; ni++) {
                    int g = ni >> 1, e = (ni & 1)*2;
                    mma16816(acc[mi][ni], ah[mi], bh[g][e], bh[g][e+1]);
                    mma16816(acc[mi][ni], ah[mi], bl[g][e], bl[g][e+1]);
                    mma16816(acc[mi][ni], al[mi], bh[g][e], bh[g][e+1]);
                }
        }
        __syncthreads();
    }

    // epilogue
    int o0 = O0 + warp_m*64;
    int n0 = N0 + warp_n*32;
    #pragma unroll
    for (int mi = 0; mi < 4; mi++)
        #pragma unroll
        for (int ni = 0; ni < 4; ni++) {
            int o  = o0 + mi*16 + (lane >> 2);
            int nn = n0 + ni*8 + (lane & 3)*2;
            size_t i00 = ((size_t)nn << 10) + o;
            size_t i10 = i00 + 1024;
            if (mode == 0) {
                g_Y[yoff + i00]     = acc[mi][ni][0];
                g_Y[yoff + i10]     = acc[mi][ni][1];
                g_Y[yoff + i00 + 8] = acc[mi][ni][2];
                g_Y[yoff + i10 + 8] = acc[mi][ni][3];
            } else {
                float s0 = g_scores[p*BB + (nn & 31)];
                float s1 = g_scores[p*BB + ((nn+1) & 31)];
                out[i00]     = fj[i00]     + s0*acc[mi][ni][0];
                out[i10]     = fj[i10]     + s1*acc[mi][ni][1];
                out[i00 + 8] = fj[i00 + 8] + s0*acc[mi][ni][2];
                out[i10 + 8] = fj[i10 + 8] + s1*acc[mi][ni][3];
            }
        }
}

// ---------------- fast-output epilogue (lerp of Y + bias + residual, or copy) ----------------
__global__ void k_epi_fast(const float* __restrict__ Fj, const float* __restrict__ bias,
                           float* __restrict__ out, int j) {
    int gid = blockIdx.x*256 + threadIdx.x;
    int n = gid >> 8;
    int o = (gid & 255) * 4;
    int t = n >> 5, b = n & 31;
    float4 fv = *(const float4*)&Fj[(size_t)n*DD + o];
    int s = sel_s2f(j);
    float4 res;
    if (s < 0) {
        res = fv;
    } else {
        int ib = s - 2;
        float sc = g_scores[(s*4 + j)*BB + b];
        float src = 0.25f*(float)t - 0.375f;
        src = fminf(fmaxf(src, 0.f), 127.f);
        float fi0 = floorf(src);
        int i0 = (int)fi0;
        int i1 = min(i0 + 1, 127);
        float w = src - fi0;
        const float* Yp = g_Y + (size_t)ib*NS;
        float4 y0 = *(const float4*)&Yp[((size_t)i0*BB + b)*DD + o];
        float4 y1 = *(const float4*)&Yp[((size_t)i1*BB + b)*DD + o];
        float4 bv = *(const float4*)&bias[o];
        float om = 1.f - w;
        res.x = fv.x + sc*(om*y0.x + w*y1.x + bv.x);
        res.y = fv.y + sc*(om*y0.y + w*y1.y + bv.y);
        res.z = fv.z + sc*(om*y0.z + w*y1.z + bv.z);
        res.w = fv.w + sc*(om*y0.w + w*y1.w + bv.w);
    }
    *(float4*)&out[(size_t)n*DD + o] = res;
}

__global__ void k_copy_slow(const float* __restrict__ fj, float* __restrict__ out, int j) {
    if (sel_f2s(j) >= 0) return;
    int gid = blockIdx.x*256 + threadIdx.x;
    ((float4*)out)[gid] = ((const float4*)fj)[gid];
}

extern "C" void kernel_launch(void* const* d_in, const int* in_sizes, int n_in,
                              void* d_out, int out_size) {
    const float* f0    = (const float*)d_in[0];
    const float* f1    = (const float*)d_in[1];
    const float* f2    = (const float*)d_in[2];
    const float* f3    = (const float*)d_in[3];
    const float* w1    = (const float*)d_in[4];
    const float* b1    = (const float*)d_in[5];
    const float* w2    = (const float*)d_in[6];
    const float* b2    = (const float*)d_in[7];
    const float* s2fw  = (const float*)d_in[8];
    const float* s2fb  = (const float*)d_in[9];
    const float* f2sw  = (const float*)d_in[10];
    float* out = (float*)d_out;

    cudaFuncSetAttribute(k_gemm, cudaFuncAttributeMaxDynamicSharedMemorySize, SMEM_TOTAL);

    k_globals<<<(4*BB*DD + 255)/256, 256>>>(f0, f1, f2, f3);
    k_mlp1<<<dim3(BB, 8), 256>>>(w1, b1);
    k_mlp2<<<8, 32>>>(w2, b2);

    // conversions (guarded on device flags)
    k_cvt_ws2f<<<1024, 256>>>(s2fw);
    k_cvt_slow<<<4096, 256>>>(f2, 0);
    k_cvt_slow<<<4096, 256>>>(f3, 1);
    k_cvt_fast<<<16384, 256>>>(f0, 0);
    k_cvt_fast<<<16384, 256>>>(f1, 1);
    k_cvt_wf2s<<<5120, 256>>>(f2sw, 0);
    k_cvt_wf2s<<<5120, 256>>>(f2sw, 1);

    // s2f: tensor-core 1x1 conv at T=128 -> g_Y, then lerp epilogues
    k_gemm<<<dim3(8,32), 256, SMEM_TOTAL>>>(0, 0, nullptr, nullptr);
    k_gemm<<<dim3(8,32), 256, SMEM_TOTAL>>>(0, 1, nullptr, nullptr);
    k_epi_fast<<<NF/4/256, 256>>>(f0, s2fb, out, 0);
    k_epi_fast<<<NF/4/256, 256>>>(f1, s2fb, out + NF, 1);

    // f2s: tensor-core strided conv with fused residual; fallback copy if unselected
    k_gemm<<<dim3(8,32), 256, SMEM_TOTAL>>>(1, 2, f2, out + 2*(size_t)NF);
    k_gemm<<<dim3(8,32), 256, SMEM_TOTAL>>>(1, 3, f3, out + 2*(size_t)NF + NS);
    k_copy_slow<<<NS/4/256, 256>>>(f2, out + 2*(size_t)NF, 2);
    k_copy_slow<<<NS/4/256, 256>>>(f3, out + 2*(size_t)NF + NS, 3);
}

// round 14
// speedup vs baseline: 2.7909x; 1.2115x over previous
#include <cuda_runtime.h>
#include <cuda_fp16.h>
#include <stdint.h>
#include <math.h>

#define T_FAST 512
#define T_SLOW 128
#define BB 32
#define DD 1024
#define HH 256
#define NF (T_FAST*BB*DD)   // 16777216
#define NS (T_SLOW*BB*DD)   // 4194304

// ---------------- static scratch (no allocs) ----------------
__device__ float g_glob[4*BB*DD];
__device__ float g_hbuf[8*BB*HH];
__device__ float g_scores[16*BB];
__device__ int   g_cond[16];
__device__ float g_Y[2*NS];
__device__ __half g_Fh[2*NF];                           // fast feats hi (slot=i)
__device__ __half g_Sh[2*NS];                           // slow feats hi (slot=i-2)
__device__ __half g_Wfh[2*5242880], g_Wfl[2*5242880];   // f2s W flat (o*5+k)*1024+c (slot=j-2)
__device__ __half g_Wsh[1024*1024], g_Wsl[1024*1024];   // s2f W [o][c]

__constant__ int c_pi[8] = {2,3,2,3,0,1,0,1};
__constant__ int c_pj[8] = {0,0,1,1,2,2,3,3};
__constant__ int c_pp[8] = {8,12,9,13,2,6,3,7};

__device__ __forceinline__ int sel_s2f(int j) {
    if (g_cond[12 + j]) return 3;
    if (g_cond[8 + j])  return 2;
    return -1;
}
__device__ __forceinline__ int sel_f2s(int j) {
    if (g_cond[4 + j]) return 1;
    if (g_cond[j])     return 0;
    return -1;
}

// ---------------- low-level helpers (family-portable: sm_80-era) ----------------
__device__ __forceinline__ uint32_t smem_u32(const void* p){
    uint32_t a;
    asm("{ .reg .u64 t; cvta.to.shared.u64 t, %1; cvt.u32.u64 %0, t; }":"=r"(a):"l"(p));
    return a;
}
__device__ __forceinline__ void cpasync16(uint32_t d, const void* g, int sz){
    asm volatile("cp.async.cg.shared.global [%0], [%1], 16, %2;"
                 :: "r"(d), "l"(g), "r"(sz) : "memory");
}
__device__ __forceinline__ void ldm_x4(uint32_t r[4], uint32_t addr){
    asm volatile("ldmatrix.sync.aligned.m8n8.x4.shared.b16 {%0,%1,%2,%3}, [%4];"
                 : "=r"(r[0]), "=r"(r[1]), "=r"(r[2]), "=r"(r[3]) : "r"(addr));
}
__device__ __forceinline__ void mma16816(float d[4], const uint32_t a[4], uint32_t b0, uint32_t b1){
    asm volatile("mma.sync.aligned.m16n8k16.row.col.f32.f16.f16.f32 "
        "{%0,%1,%2,%3}, {%4,%5,%6,%7}, {%8,%9}, {%0,%1,%2,%3};"
        : "+f"(d[0]), "+f"(d[1]), "+f"(d[2]), "+f"(d[3])
        : "r"(a[0]), "r"(a[1]), "r"(a[2]), "r"(a[3]), "r"(b0), "r"(b1));
}

// smem: 3 arrays x 128 rows x 40 halves (80B padded stride), double buffered
#define ROWB 80
#define ARR_SZ 10240
#define OFF_AH 0
#define OFF_AL 10240
#define OFF_BH 20480
#define BUF_SZ 30720
#define SMEM_TOTAL (2*BUF_SZ)

// ---------------- conversions ----------------
__device__ __forceinline__ void cvt_store4h(float4 v, __half* ph, __half* pl){
    __half h0=__float2half_rn(v.x), h1=__float2half_rn(v.y);
    __half h2=__float2half_rn(v.z), h3=__float2half_rn(v.w);
    __half l0=__float2half_rn(v.x-__half2float(h0));
    __half l1=__float2half_rn(v.y-__half2float(h1));
    __half l2=__float2half_rn(v.z-__half2float(h2));
    __half l3=__float2half_rn(v.w-__half2float(h3));
    union { __half b[4]; uint2 u; } H, L;
    H.b[0]=h0; H.b[1]=h1; H.b[2]=h2; H.b[3]=h3;
    L.b[0]=l0; L.b[1]=l1; L.b[2]=l2; L.b[3]=l3;
    *(uint2*)ph = H.u;
    *(uint2*)pl = L.u;
}
__device__ __forceinline__ void cvt_store4hi(float4 v, __half* ph){
    union { __half b[4]; uint2 u; } H;
    H.b[0]=__float2half_rn(v.x); H.b[1]=__float2half_rn(v.y);
    H.b[2]=__float2half_rn(v.z); H.b[3]=__float2half_rn(v.w);
    *(uint2*)ph = H.u;
}
__global__ void k_cvt_fast(const float* __restrict__ f, int i) {
    if (sel_f2s(2) != i && sel_f2s(3) != i) return;
    size_t idx = ((size_t)blockIdx.x*256 + threadIdx.x)*4;
    float4 v = *(const float4*)(f + idx);
    cvt_store4hi(v, g_Fh + (size_t)i*NF + idx);
}
__global__ void k_cvt_slow(const float* __restrict__ f, int ib) {
    int i = 2 + ib;
    if (sel_s2f(0) != i && sel_s2f(1) != i) return;
    size_t idx = ((size_t)blockIdx.x*256 + threadIdx.x)*4;
    float4 v = *(const float4*)(f + idx);
    cvt_store4hi(v, g_Sh + (size_t)ib*NS + idx);
}
__global__ void k_cvt_ws2f(const float* __restrict__ w) {
    if (sel_s2f(0) < 0 && sel_s2f(1) < 0) return;
    size_t idx = ((size_t)blockIdx.x*256 + threadIdx.x)*4;
    float4 v = *(const float4*)(w + idx);
    cvt_store4h(v, g_Wsh + idx, g_Wsl + idx);
}
__global__ void k_cvt_wf2s(const float* __restrict__ wAll, int jb) {
    int j = 2 + jb;
    int s = sel_f2s(j);
    if (s < 0) return;
    int g = s*2 + jb;                                   // F2S_IDX[(s, j)]
    size_t flat = ((size_t)blockIdx.x*256 + threadIdx.x)*4;  // (o*5+k)*1024 + c
    int c  = (int)(flat & 1023);
    int ok = (int)(flat >> 10);
    int o = ok / 5, k = ok % 5;
    const float* src = wAll + ((size_t)(g*1024 + o)*1024 + c)*5 + k;
    float4 v = make_float4(src[0], src[5], src[10], src[15]);
    cvt_store4h(v, g_Wfh + (size_t)jb*5242880 + flat, g_Wfl + (size_t)jb*5242880 + flat);
}

// ---------------- K1: time means ----------------
__global__ void k_globals(const float* __restrict__ f0, const float* __restrict__ f1,
                          const float* __restrict__ f2, const float* __restrict__ f3) {
    int idx = blockIdx.x*blockDim.x + threadIdx.x;
    if (idx >= 4*BB*DD) return;
    int i  = idx >> 15;
    int bd = idx & 32767;
    int b = bd >> 10, d = bd & 1023;
    const float* f = (i==0)?f0:(i==1)?f1:(i==2)?f2:f3;
    int T = (i < 2) ? T_FAST : T_SLOW;
    float s = 0.f;
    for (int t = 0; t < T; t++) s += f[((size_t)t*BB + b)*DD + d];
    g_glob[idx] = s / (float)T;
}

// ---------------- K2: gating MLP ----------------
__global__ void k_mlp1(const float* __restrict__ w1, const float* __restrict__ b1) {
    __shared__ float pv[2*DD];
    int b = blockIdx.x, lp = blockIdx.y, tid = threadIdx.x;
    int i = c_pi[lp], j = c_pj[lp], p = c_pp[lp];
    for (int c = tid; c < 2*DD; c += 256)
        pv[c] = (c < DD) ? g_glob[(i*BB+b)*DD + c] : g_glob[(j*BB+b)*DD + (c-DD)];
    __syncthreads();
    const float* w = w1 + (size_t)p*2*DD*HH + tid;
    float acc = b1[p*HH + tid];
    #pragma unroll 8
    for (int c = 0; c < 2*DD; c++) acc += pv[c] * w[(size_t)c*HH];
    g_hbuf[(lp*BB + b)*HH + tid] = fmaxf(acc, 0.f);
}
__global__ void k_mlp2(const float* __restrict__ w2, const float* __restrict__ b2) {
    int lp = blockIdx.x, b = threadIdx.x, p = c_pp[lp];
    const float* hb = g_hbuf + (lp*BB + b)*HH;
    const float* w  = w2 + p*HH;
    float acc = 0.f;
    #pragma unroll 8
    for (int h = 0; h < HH; h++) acc += hb[h]*w[h];
    float s = 1.f/(1.f + expf(-(acc + b2[p])));
    g_scores[p*BB + b] = s;
    float sum = s;
    #pragma unroll
    for (int o = 16; o; o >>= 1) sum += __shfl_xor_sync(0xffffffffu, sum, o);
    if (b == 0) g_cond[p] = (sum * (1.f/32.f) >= 0.3f) ? 1 : 0;
}

// ---------------- unified mma.sync GEMM (2-term split: (Ah+Al)*Bh) ----------------
// mode 0: s2f 1x1 conv at T=128 (K=1024), writes raw g_Y[jarg].
// mode 1: f2s strided conv (5 taps, K=5120), fused residual into out.
// Tiles: CTA 128(M=o) x 128(N=n), 8 warps (2M x 4N), warp 64x32.
__device__ __forceinline__ void issue_stage(uint32_t sb, const __half* __restrict__ Ah,
        const __half* __restrict__ Al, const __half* __restrict__ Bh,
        int mode, int O0, int N0, int s, int tid) {
    int k  = mode ? (s >> 5) : 0;
    int c0 = mode ? ((s & 31) << 5) : (s << 5);
    int Tsrc = mode ? T_FAST : T_SLOW;
    #pragma unroll
    for (int h = 0; h < 2; h++) {
        int q = tid + h*256;
        int r = q >> 2, c = q & 3;
        uint32_t doff = (uint32_t)(r*ROWB + c*16);
        size_t aoff = mode ? ((((size_t)(O0+r)*5 + k) << 10) + c0 + c*8)
                           : (((size_t)(O0+r) << 10) + c0 + c*8);
        cpasync16(sb + OFF_AH + doff, Ah + aoff, 16);
        cpasync16(sb + OFF_AL + doff, Al + aoff, 16);
        int n = N0 + r;
        int t_ = mode ? (4*(n>>5) + k - 2) : (n>>5);
        int b_ = n & 31;
        bool ok = (t_ >= 0) && (t_ < Tsrc);
        size_t boff = (((size_t)(ok ? t_ : 0)*BB + b_) << 10) + c0 + c*8;
        cpasync16(sb + OFF_BH + doff, Bh + boff, ok ? 16 : 0);
    }
}

__global__ void __launch_bounds__(256) k_gemm(int mode, int jarg,
                                              const float* __restrict__ fj,
                                              float* __restrict__ out) {
    const __half *Ah, *Al, *Bh;
    int p = 0;
    size_t yoff = 0;
    if (mode == 0) {
        int i = 2 + jarg;
        if (sel_s2f(0) != i && sel_s2f(1) != i) return;
        Ah = g_Wsh; Al = g_Wsl;
        Bh = g_Sh + (size_t)jarg*NS;
        yoff = (size_t)jarg*NS;
    } else {
        int s = sel_f2s(jarg);
        if (s < 0) return;
        int jb = jarg - 2;
        Ah = g_Wfh + (size_t)jb*5242880; Al = g_Wfl + (size_t)jb*5242880;
        Bh = g_Fh + (size_t)s*NF;
        p = s*4 + jarg;
    }

    extern __shared__ char sm[];
    uint32_t smem_base = smem_u32(sm);
    int tid = threadIdx.x;
    int lane = tid & 31, wid = tid >> 5;
    int warp_m = wid & 1, warp_n = wid >> 1;
    int O0 = blockIdx.x * 128;
    int N0 = blockIdx.y * 128;

    // ldmatrix per-lane base offsets
    int a_row = warp_m*64 + (lane & 7) + ((lane >> 3) & 1)*8;
    int a_cb  = lane >> 4;                 // k-chunk offset (16B units)
    int b_row = warp_n*32 + (lane & 7) + (lane >> 4)*8;
    int b_cb  = (lane >> 3) & 1;

    float acc[4][4][4];
    #pragma unroll
    for (int mi = 0; mi < 4; mi++)
        #pragma unroll
        for (int ni = 0; ni < 4; ni++)
            #pragma unroll
            for (int e = 0; e < 4; e++) acc[mi][ni][e] = 0.f;

    int NSt = mode ? 160 : 32;
    issue_stage(smem_base, Ah, Al, Bh, mode, O0, N0, 0, tid);
    asm volatile("cp.async.commit_group;" ::: "memory");

    for (int s = 0; s < NSt; s++) {
        if (s + 1 < NSt) {
            issue_stage(smem_base + ((s+1)&1)*BUF_SZ, Ah, Al, Bh, mode, O0, N0, s+1, tid);
            asm volatile("cp.async.commit_group;" ::: "memory");
            asm volatile("cp.async.wait_group 1;" ::: "memory");
        } else {
            asm volatile("cp.async.wait_group 0;" ::: "memory");
        }
        __syncthreads();

        uint32_t sb = smem_base + (s&1)*BUF_SZ;
        #pragma unroll
        for (int kk8 = 0; kk8 <= 2; kk8 += 2) {
            uint32_t ah[4][4], al[4][4], bh[2][4];
            #pragma unroll
            for (int mi = 0; mi < 4; mi++) {
                uint32_t ad = sb + (uint32_t)((a_row + mi*16)*ROWB + (kk8 + a_cb)*16);
                ldm_x4(ah[mi], ad + OFF_AH);
                ldm_x4(al[mi], ad + OFF_AL);
            }
            #pragma unroll
            for (int g = 0; g < 2; g++) {
                uint32_t bd = sb + (uint32_t)((b_row + g*16)*ROWB + (kk8 + b_cb)*16);
                ldm_x4(bh[g], bd + OFF_BH);
            }
            #pragma unroll
            for (int mi = 0; mi < 4; mi++)
                #pragma unroll
                for (int ni = 0; ni < 4; ni++) {
                    int g = ni >> 1, e = (ni & 1)*2;
                    mma16816(acc[mi][ni], ah[mi], bh[g][e], bh[g][e+1]);
                    mma16816(acc[mi][ni], al[mi], bh[g][e], bh[g][e+1]);
                }
        }
        __syncthreads();
    }

    // epilogue
    int o0 = O0 + warp_m*64;
    int n0 = N0 + warp_n*32;
    #pragma unroll
    for (int mi = 0; mi < 4; mi++)
        #pragma unroll
        for (int ni = 0; ni < 4; ni++) {
            int o  = o0 + mi*16 + (lane >> 2);
            int nn = n0 + ni*8 + (lane & 3)*2;
            size_t i00 = ((size_t)nn << 10) + o;
            size_t i10 = i00 + 1024;
            if (mode == 0) {
                g_Y[yoff + i00]     = acc[mi][ni][0];
                g_Y[yoff + i10]     = acc[mi][ni][1];
                g_Y[yoff + i00 + 8] = acc[mi][ni][2];
                g_Y[yoff + i10 + 8] = acc[mi][ni][3];
            } else {
                float s0 = g_scores[p*BB + (nn & 31)];
                float s1 = g_scores[p*BB + ((nn+1) & 31)];
                out[i00]     = fj[i00]     + s0*acc[mi][ni][0];
                out[i10]     = fj[i10]     + s1*acc[mi][ni][1];
                out[i00 + 8] = fj[i00 + 8] + s0*acc[mi][ni][2];
                out[i10 + 8] = fj[i10 + 8] + s1*acc[mi][ni][3];
            }
        }
}

// ---------------- fast-output epilogue (lerp of Y + bias + residual, or copy) ----------------
__global__ void k_epi_fast(const float* __restrict__ Fj, const float* __restrict__ bias,
                           float* __restrict__ out, int j) {
    int gid = blockIdx.x*256 + threadIdx.x;
    int n = gid >> 8;
    int o = (gid & 255) * 4;
    int t = n >> 5, b = n & 31;
    float4 fv = *(const float4*)&Fj[(size_t)n*DD + o];
    int s = sel_s2f(j);
    float4 res;
    if (s < 0) {
        res = fv;
    } else {
        int ib = s - 2;
        float sc = g_scores[(s*4 + j)*BB + b];
        float src = 0.25f*(float)t - 0.375f;
        src = fminf(fmaxf(src, 0.f), 127.f);
        float fi0 = floorf(src);
        int i0 = (int)fi0;
        int i1 = min(i0 + 1, 127);
        float w = src - fi0;
        const float* Yp = g_Y + (size_t)ib*NS;
        float4 y0 = *(const float4*)&Yp[((size_t)i0*BB + b)*DD + o];
        float4 y1 = *(const float4*)&Yp[((size_t)i1*BB + b)*DD + o];
        float4 bv = *(const float4*)&bias[o];
        float om = 1.f - w;
        res.x = fv.x + sc*(om*y0.x + w*y1.x + bv.x);
        res.y = fv.y + sc*(om*y0.y + w*y1.y + bv.y);
        res.z = fv.z + sc*(om*y0.z + w*y1.z + bv.z);
        res.w = fv.w + sc*(om*y0.w + w*y1.w + bv.w);
    }
    *(float4*)&out[(size_t)n*DD + o] = res;
}

__global__ void k_copy_slow(const float* __restrict__ fj, float* __restrict__ out, int j) {
    if (sel_f2s(j) >= 0) return;
    int gid = blockIdx.x*256 + threadIdx.x;
    ((float4*)out)[gid] = ((const float4*)fj)[gid];
}

extern "C" void kernel_launch(void* const* d_in, const int* in_sizes, int n_in,
                              void* d_out, int out_size) {
    const float* f0    = (const float*)d_in[0];
    const float* f1    = (const float*)d_in[1];
    const float* f2    = (const float*)d_in[2];
    const float* f3    = (const float*)d_in[3];
    const float* w1    = (const float*)d_in[4];
    const float* b1    = (const float*)d_in[5];
    const float* w2    = (const float*)d_in[6];
    const float* b2    = (const float*)d_in[7];
    const float* s2fw  = (const float*)d_in[8];
    const float* s2fb  = (const float*)d_in[9];
    const float* f2sw  = (const float*)d_in[10];
    float* out = (float*)d_out;

    cudaFuncSetAttribute(k_gemm, cudaFuncAttributeMaxDynamicSharedMemorySize, SMEM_TOTAL);

    k_globals<<<(4*BB*DD + 255)/256, 256>>>(f0, f1, f2, f3);
    k_mlp1<<<dim3(BB, 8), 256>>>(w1, b1);
    k_mlp2<<<8, 32>>>(w2, b2);

    // conversions (guarded on device flags)
    k_cvt_ws2f<<<1024, 256>>>(s2fw);
    k_cvt_slow<<<4096, 256>>>(f2, 0);
    k_cvt_slow<<<4096, 256>>>(f3, 1);
    k_cvt_fast<<<16384, 256>>>(f0, 0);
    k_cvt_fast<<<16384, 256>>>(f1, 1);
    k_cvt_wf2s<<<5120, 256>>>(f2sw, 0);
    k_cvt_wf2s<<<5120, 256>>>(f2sw, 1);

    // s2f: tensor-core 1x1 conv at T=128 -> g_Y, then lerp epilogues
    k_gemm<<<dim3(8,32), 256, SMEM_TOTAL>>>(0, 0, nullptr, nullptr);
    k_gemm<<<dim3(8,32), 256, SMEM_TOTAL>>>(0, 1, nullptr, nullptr);
    k_epi_fast<<<NF/4/256, 256>>>(f0, s2fb, out, 0);
    k_epi_fast<<<NF/4/256, 256>>>(f1, s2fb, out + NF, 1);

    // f2s: tensor-core strided conv with fused residual; fallback copy if unselected
    k_gemm<<<dim3(8,32), 256, SMEM_TOTAL>>>(1, 2, f2, out + 2*(size_t)NF);
    k_gemm<<<dim3(8,32), 256, SMEM_TOTAL>>>(1, 3, f3, out + 2*(size_t)NF + NS);
    k_copy_slow<<<NS/4/256, 256>>>(f2, out + 2*(size_t)NF, 2);
    k_copy_slow<<<NS/4/256, 256>>>(f3, out + 2*(size_t)NF + NS, 3);
}

// round 15
// speedup vs baseline: 3.8880x; 1.3931x over previous
#include <cuda_runtime.h>
#include <cuda_fp16.h>
#include <stdint.h>
#include <math.h>

#define T_FAST 512
#define T_SLOW 128
#define BB 32
#define DD 1024
#define HH 256
#define NF (T_FAST*BB*DD)   // 16777216
#define NS (T_SLOW*BB*DD)   // 4194304

// ---------------- static scratch (no allocs) ----------------
__device__ float g_glob[4*BB*DD];
__device__ float g_hbuf[8*BB*HH];
__device__ float g_scores[16*BB];
__device__ int   g_cond[16];
__device__ float g_Y[2*NS];
__device__ __half g_Fh[2*NF];                 // fast feats (slot=i)
__device__ __half g_Sh[2*NS];                 // slow feats (slot=i-2)
__device__ __half g_Wfh[2*5242880];           // f2s W flat (o*5+k)*1024+c (slot=j-2)
__device__ __half g_Wsh[1024*1024];           // s2f W [o][c]

__constant__ int c_pi[8] = {2,3,2,3,0,1,0,1};
__constant__ int c_pj[8] = {0,0,1,1,2,2,3,3};
__constant__ int c_pp[8] = {8,12,9,13,2,6,3,7};

__device__ __forceinline__ int sel_s2f(int j) {
    if (g_cond[12 + j]) return 3;
    if (g_cond[8 + j])  return 2;
    return -1;
}
__device__ __forceinline__ int sel_f2s(int j) {
    if (g_cond[4 + j]) return 1;
    if (g_cond[j])     return 0;
    return -1;
}

// ---------------- low-level helpers (family-portable: sm_80-era) ----------------
__device__ __forceinline__ uint32_t smem_u32(const void* p){
    uint32_t a;
    asm("{ .reg .u64 t; cvta.to.shared.u64 t, %1; cvt.u32.u64 %0, t; }":"=r"(a):"l"(p));
    return a;
}
__device__ __forceinline__ void cpasync16(uint32_t d, const void* g, int sz){
    asm volatile("cp.async.cg.shared.global [%0], [%1], 16, %2;"
                 :: "r"(d), "l"(g), "r"(sz) : "memory");
}
__device__ __forceinline__ void ldm_x4(uint32_t r[4], uint32_t addr){
    asm volatile("ldmatrix.sync.aligned.m8n8.x4.shared.b16 {%0,%1,%2,%3}, [%4];"
                 : "=r"(r[0]), "=r"(r[1]), "=r"(r[2]), "=r"(r[3]) : "r"(addr));
}
__device__ __forceinline__ void mma16816(float d[4], const uint32_t a[4], uint32_t b0, uint32_t b1){
    asm volatile("mma.sync.aligned.m16n8k16.row.col.f32.f16.f16.f32 "
        "{%0,%1,%2,%3}, {%4,%5,%6,%7}, {%8,%9}, {%0,%1,%2,%3};"
        : "+f"(d[0]), "+f"(d[1]), "+f"(d[2]), "+f"(d[3])
        : "r"(a[0]), "r"(a[1]), "r"(a[2]), "r"(a[3]), "r"(b0), "r"(b1));
}

// smem: 2 arrays x 128 rows x 40 halves (80B padded stride), double buffered
#define ROWB 80
#define OFF_AH 0
#define OFF_BH 10240
#define BUF_SZ 20480
#define SMEM_TOTAL (2*BUF_SZ)

// ---------------- conversions (fp16, round-to-nearest) ----------------
__device__ __forceinline__ void cvt_store4hi(float4 v, __half* ph){
    union { __half b[4]; uint2 u; } H;
    H.b[0]=__float2half_rn(v.x); H.b[1]=__float2half_rn(v.y);
    H.b[2]=__float2half_rn(v.z); H.b[3]=__float2half_rn(v.w);
    *(uint2*)ph = H.u;
}
__global__ void k_cvt_fast(const float* __restrict__ f, int i) {
    if (sel_f2s(2) != i && sel_f2s(3) != i) return;
    size_t idx = ((size_t)blockIdx.x*256 + threadIdx.x)*4;
    float4 v = *(const float4*)(f + idx);
    cvt_store4hi(v, g_Fh + (size_t)i*NF + idx);
}
__global__ void k_cvt_slow(const float* __restrict__ f, int ib) {
    int i = 2 + ib;
    if (sel_s2f(0) != i && sel_s2f(1) != i) return;
    size_t idx = ((size_t)blockIdx.x*256 + threadIdx.x)*4;
    float4 v = *(const float4*)(f + idx);
    cvt_store4hi(v, g_Sh + (size_t)ib*NS + idx);
}
__global__ void k_cvt_ws2f(const float* __restrict__ w) {
    if (sel_s2f(0) < 0 && sel_s2f(1) < 0) return;
    size_t idx = ((size_t)blockIdx.x*256 + threadIdx.x)*4;
    float4 v = *(const float4*)(w + idx);
    cvt_store4hi(v, g_Wsh + idx);
}
__global__ void k_cvt_wf2s(const float* __restrict__ wAll, int jb) {
    int j = 2 + jb;
    int s = sel_f2s(j);
    if (s < 0) return;
    int g = s*2 + jb;                                   // F2S_IDX[(s, j)]
    size_t flat = ((size_t)blockIdx.x*256 + threadIdx.x)*4;  // (o*5+k)*1024 + c
    int c  = (int)(flat & 1023);
    int ok = (int)(flat >> 10);
    int o = ok / 5, k = ok % 5;
    const float* src = wAll + ((size_t)(g*1024 + o)*1024 + c)*5 + k;
    float4 v = make_float4(src[0], src[5], src[10], src[15]);
    cvt_store4hi(v, g_Wfh + (size_t)jb*5242880 + flat);
}

// ---------------- K1: time means ----------------
__global__ void k_globals(const float* __restrict__ f0, const float* __restrict__ f1,
                          const float* __restrict__ f2, const float* __restrict__ f3) {
    int idx = blockIdx.x*blockDim.x + threadIdx.x;
    if (idx >= 4*BB*DD) return;
    int i  = idx >> 15;
    int bd = idx & 32767;
    int b = bd >> 10, d = bd & 1023;
    const float* f = (i==0)?f0:(i==1)?f1:(i==2)?f2:f3;
    int T = (i < 2) ? T_FAST : T_SLOW;
    float s = 0.f;
    for (int t = 0; t < T; t++) s += f[((size_t)t*BB + b)*DD + d];
    g_glob[idx] = s / (float)T;
}

// ---------------- K2: gating MLP ----------------
__global__ void k_mlp1(const float* __restrict__ w1, const float* __restrict__ b1) {
    __shared__ float pv[2*DD];
    int b = blockIdx.x, lp = blockIdx.y, tid = threadIdx.x;
    int i = c_pi[lp], j = c_pj[lp], p = c_pp[lp];
    for (int c = tid; c < 2*DD; c += 256)
        pv[c] = (c < DD) ? g_glob[(i*BB+b)*DD + c] : g_glob[(j*BB+b)*DD + (c-DD)];
    __syncthreads();
    const float* w = w1 + (size_t)p*2*DD*HH + tid;
    float acc = b1[p*HH + tid];
    #pragma unroll 8
    for (int c = 0; c < 2*DD; c++) acc += pv[c] * w[(size_t)c*HH];
    g_hbuf[(lp*BB + b)*HH + tid] = fmaxf(acc, 0.f);
}
__global__ void k_mlp2(const float* __restrict__ w2, const float* __restrict__ b2) {
    int lp = blockIdx.x, b = threadIdx.x, p = c_pp[lp];
    const float* hb = g_hbuf + (lp*BB + b)*HH;
    const float* w  = w2 + p*HH;
    float acc = 0.f;
    #pragma unroll 8
    for (int h = 0; h < HH; h++) acc += hb[h]*w[h];
    float s = 1.f/(1.f + expf(-(acc + b2[p])));
    g_scores[p*BB + b] = s;
    float sum = s;
    #pragma unroll
    for (int o = 16; o; o >>= 1) sum += __shfl_xor_sync(0xffffffffu, sum, o);
    if (b == 0) g_cond[p] = (sum * (1.f/32.f) >= 0.3f) ? 1 : 0;
}

// ---------------- unified mma.sync GEMM (pure fp16 single term) ----------------
// mode 0: s2f 1x1 conv at T=128 (K=1024), writes raw g_Y[jarg].
// mode 1: f2s strided conv (5 taps, K=5120), fused residual into out.
// Tiles: CTA 128(M=o) x 128(N=n), 8 warps (2M x 4N), warp 64x32.
__device__ __forceinline__ void issue_stage(uint32_t sb, const __half* __restrict__ Ah,
        const __half* __restrict__ Bh,
        int mode, int O0, int N0, int s, int tid) {
    int k  = mode ? (s >> 5) : 0;
    int c0 = mode ? ((s & 31) << 5) : (s << 5);
    int Tsrc = mode ? T_FAST : T_SLOW;
    #pragma unroll
    for (int h = 0; h < 2; h++) {
        int q = tid + h*256;
        int r = q >> 2, c = q & 3;
        uint32_t doff = (uint32_t)(r*ROWB + c*16);
        size_t aoff = mode ? ((((size_t)(O0+r)*5 + k) << 10) + c0 + c*8)
                           : (((size_t)(O0+r) << 10) + c0 + c*8);
        cpasync16(sb + OFF_AH + doff, Ah + aoff, 16);
        int n = N0 + r;
        int t_ = mode ? (4*(n>>5) + k - 2) : (n>>5);
        int b_ = n & 31;
        bool ok = (t_ >= 0) && (t_ < Tsrc);
        size_t boff = (((size_t)(ok ? t_ : 0)*BB + b_) << 10) + c0 + c*8;
        cpasync16(sb + OFF_BH + doff, Bh + boff, ok ? 16 : 0);
    }
}

__global__ void __launch_bounds__(256) k_gemm(int mode, int jarg,
                                              const float* __restrict__ fj,
                                              float* __restrict__ out) {
    const __half *Ah, *Bh;
    int p = 0;
    size_t yoff = 0;
    if (mode == 0) {
        int i = 2 + jarg;
        if (sel_s2f(0) != i && sel_s2f(1) != i) return;
        Ah = g_Wsh;
        Bh = g_Sh + (size_t)jarg*NS;
        yoff = (size_t)jarg*NS;
    } else {
        int s = sel_f2s(jarg);
        if (s < 0) return;
        int jb = jarg - 2;
        Ah = g_Wfh + (size_t)jb*5242880;
        Bh = g_Fh + (size_t)s*NF;
        p = s*4 + jarg;
    }

    extern __shared__ char sm[];
    uint32_t smem_base = smem_u32(sm);
    int tid = threadIdx.x;
    int lane = tid & 31, wid = tid >> 5;
    int warp_m = wid & 1, warp_n = wid >> 1;
    int O0 = blockIdx.x * 128;
    int N0 = blockIdx.y * 128;

    // ldmatrix per-lane base offsets
    int a_row = warp_m*64 + (lane & 7) + ((lane >> 3) & 1)*8;
    int a_cb  = lane >> 4;                 // k-chunk offset (16B units)
    int b_row = warp_n*32 + (lane & 7) + (lane >> 4)*8;
    int b_cb  = (lane >> 3) & 1;

    float acc[4][4][4];
    #pragma unroll
    for (int mi = 0; mi < 4; mi++)
        #pragma unroll
        for (int ni = 0; ni < 4; ni++)
            #pragma unroll
            for (int e = 0; e < 4; e++) acc[mi][ni][e] = 0.f;

    int NSt = mode ? 160 : 32;
    issue_stage(smem_base, Ah, Bh, mode, O0, N0, 0, tid);
    asm volatile("cp.async.commit_group;" ::: "memory");

    for (int s = 0; s < NSt; s++) {
        if (s + 1 < NSt) {
            issue_stage(smem_base + ((s+1)&1)*BUF_SZ, Ah, Bh, mode, O0, N0, s+1, tid);
            asm volatile("cp.async.commit_group;" ::: "memory");
            asm volatile("cp.async.wait_group 1;" ::: "memory");
        } else {
            asm volatile("cp.async.wait_group 0;" ::: "memory");
        }
        __syncthreads();

        uint32_t sb = smem_base + (s&1)*BUF_SZ;
        #pragma unroll
        for (int kk8 = 0; kk8 <= 2; kk8 += 2) {
            uint32_t ah[4][4], bh[2][4];
            #pragma unroll
            for (int mi = 0; mi < 4; mi++) {
                uint32_t ad = sb + (uint32_t)((a_row + mi*16)*ROWB + (kk8 + a_cb)*16);
                ldm_x4(ah[mi], ad + OFF_AH);
            }
            #pragma unroll
            for (int g = 0; g < 2; g++) {
                uint32_t bd = sb + (uint32_t)((b_row + g*16)*ROWB + (kk8 + b_cb)*16);
                ldm_x4(bh[g], bd + OFF_BH);
            }
            #pragma unroll
            for (int mi = 0; mi < 4; mi++)
                #pragma unroll
                for (int ni = 0; ni < 4; ni++) {
                    int g = ni >> 1, e = (ni & 1)*2;
                    mma16816(acc[mi][ni], ah[mi], bh[g][e], bh[g][e+1]);
                }
        }
        __syncthreads();
    }

    // epilogue
    int o0 = O0 + warp_m*64;
    int n0 = N0 + warp_n*32;
    #pragma unroll
    for (int mi = 0; mi < 4; mi++)
        #pragma unroll
        for (int ni = 0; ni < 4; ni++) {
            int o  = o0 + mi*16 + (lane >> 2);
            int nn = n0 + ni*8 + (lane & 3)*2;
            size_t i00 = ((size_t)nn << 10) + o;
            size_t i10 = i00 + 1024;
            if (mode == 0) {
                g_Y[yoff + i00]     = acc[mi][ni][0];
                g_Y[yoff + i10]     = acc[mi][ni][1];
                g_Y[yoff + i00 + 8] = acc[mi][ni][2];
                g_Y[yoff + i10 + 8] = acc[mi][ni][3];
            } else {
                float s0 = g_scores[p*BB + (nn & 31)];
                float s1 = g_scores[p*BB + ((nn+1) & 31)];
                out[i00]     = fj[i00]     + s0*acc[mi][ni][0];
                out[i10]     = fj[i10]     + s1*acc[mi][ni][1];
                out[i00 + 8] = fj[i00 + 8] + s0*acc[mi][ni][2];
                out[i10 + 8] = fj[i10 + 8] + s1*acc[mi][ni][3];
            }
        }
}

// ---------------- fast-output epilogue (lerp of Y + bias + residual, or copy) ----------------
__global__ void k_epi_fast(const float* __restrict__ Fj, const float* __restrict__ bias,
                           float* __restrict__ out, int j) {
    int gid = blockIdx.x*256 + threadIdx.x;
    int n = gid >> 8;
    int o = (gid & 255) * 4;
    int t = n >> 5, b = n & 31;
    float4 fv = *(const float4*)&Fj[(size_t)n*DD + o];
    int s = sel_s2f(j);
    float4 res;
    if (s < 0) {
        res = fv;
    } else {
        int ib = s - 2;
        float sc = g_scores[(s*4 + j)*BB + b];
        float src = 0.25f*(float)t - 0.375f;
        src = fminf(fmaxf(src, 0.f), 127.f);
        float fi0 = floorf(src);
        int i0 = (int)fi0;
        int i1 = min(i0 + 1, 127);
        float w = src - fi0;
        const float* Yp = g_Y + (size_t)ib*NS;
        float4 y0 = *(const float4*)&Yp[((size_t)i0*BB + b)*DD + o];
        float4 y1 = *(const float4*)&Yp[((size_t)i1*BB + b)*DD + o];
        float4 bv = *(const float4*)&bias[o];
        float om = 1.f - w;
        res.x = fv.x + sc*(om*y0.x + w*y1.x + bv.x);
        res.y = fv.y + sc*(om*y0.y + w*y1.y + bv.y);
        res.z = fv.z + sc*(om*y0.z + w*y1.z + bv.z);
        res.w = fv.w + sc*(om*y0.w + w*y1.w + bv.w);
    }
    *(float4*)&out[(size_t)n*DD + o] = res;
}

__global__ void k_copy_slow(const float* __restrict__ fj, float* __restrict__ out, int j) {
    if (sel_f2s(j) >= 0) return;
    int gid = blockIdx.x*256 + threadIdx.x;
    ((float4*)out)[gid] = ((const float4*)fj)[gid];
}

extern "C" void kernel_launch(void* const* d_in, const int* in_sizes, int n_in,
                              void* d_out, int out_size) {
    const float* f0    = (const float*)d_in[0];
    const float* f1    = (const float*)d_in[1];
    const float* f2    = (const float*)d_in[2];
    const float* f3    = (const float*)d_in[3];
    const float* w1    = (const float*)d_in[4];
    const float* b1    = (const float*)d_in[5];
    const float* w2    = (const float*)d_in[6];
    const float* b2    = (const float*)d_in[7];
    const float* s2fw  = (const float*)d_in[8];
    const float* s2fb  = (const float*)d_in[9];
    const float* f2sw  = (const float*)d_in[10];
    float* out = (float*)d_out;

    cudaFuncSetAttribute(k_gemm, cudaFuncAttributeMaxDynamicSharedMemorySize, SMEM_TOTAL);

    k_globals<<<(4*BB*DD + 255)/256, 256>>>(f0, f1, f2, f3);
    k_mlp1<<<dim3(BB, 8), 256>>>(w1, b1);
    k_mlp2<<<8, 32>>>(w2, b2);

    // conversions (guarded on device flags)
    k_cvt_ws2f<<<1024, 256>>>(s2fw);
    k_cvt_slow<<<4096, 256>>>(f2, 0);
    k_cvt_slow<<<4096, 256>>>(f3, 1);
    k_cvt_fast<<<16384, 256>>>(f0, 0);
    k_cvt_fast<<<16384, 256>>>(f1, 1);
    k_cvt_wf2s<<<5120, 256>>>(f2sw, 0);
    k_cvt_wf2s<<<5120, 256>>>(f2sw, 1);

    // s2f: tensor-core 1x1 conv at T=128 -> g_Y, then lerp epilogues
    k_gemm<<<dim3(8,32), 256, SMEM_TOTAL>>>(0, 0, nullptr, nullptr);
    k_gemm<<<dim3(8,32), 256, SMEM_TOTAL>>>(0, 1, nullptr, nullptr);
    k_epi_fast<<<NF/4/256, 256>>>(f0, s2fb, out, 0);
    k_epi_fast<<<NF/4/256, 256>>>(f1, s2fb, out + NF, 1);

    // f2s: tensor-core strided conv with fused residual; fallback copy if unselected
    k_gemm<<<dim3(8,32), 256, SMEM_TOTAL>>>(1, 2, f2, out + 2*(size_t)NF);
    k_gemm<<<dim3(8,32), 256, SMEM_TOTAL>>>(1, 3, f3, out + 2*(size_t)NF + NS);
    k_copy_slow<<<NS/4/256, 256>>>(f2, out + 2*(size_t)NF, 2);
    k_copy_slow<<<NS/4/256, 256>>>(f3, out + 2*(size_t)NF + NS, 3);
}